// round 10
// baseline (speedup 1.0000x reference)
#include <cuda_runtime.h>
#include <math_constants.h>

#define MDATA 250000
#define NPH 4
#define NK 6
#define NMC 64
#define KN (NK*NMC)            // 384
#define NROWS (NPH+NK)

#define NUI 96
#define NVI 32
#define NUN (NUI+1)            // 97
#define NVN (NVI+1)            // 33
#define NODES (NUN*NVN)        // 3201 -> 50 KB table

#define V0C 0.01f
#define HUC (1.0f/96.0f)
#define HVC (0.3f/32.0f)

#define TPB 512
#define OCC 3
#define NBLK (152*OCC)         // 456 blocks, 3/SM, all co-resident

__device__ float4 g_table[NODES];
__device__ float  g_partials[NBLK];
__device__ unsigned int g_sync  = 0;
__device__ unsigned int g_count = 0;

__device__ __forceinline__ float fex2(float x) {
    float y; asm("ex2.approx.ftz.f32 %0, %1;" : "=f"(y) : "f"(x)); return y;
}
__device__ __forceinline__ float flg2(float x) {
    float y; asm("lg2.approx.ftz.f32 %0, %1;" : "=f"(y) : "f"(x)); return y;
}
__device__ __forceinline__ float frcp(float x) {
    float y; asm("rcp.approx.ftz.f32 %0, %1;" : "=f"(y) : "f"(x)); return y;
}
__device__ __forceinline__ unsigned int ld_acq(const unsigned int* p) {
    unsigned int v;
    asm volatile("ld.global.acquire.gpu.u32 %0, [%1];" : "=r"(v) : "l"(p));
    return v;
}

__global__ void __launch_bounds__(TPB, OCC) bimm_fused_kernel(
    const float* __restrict__ gu, const float* __restrict__ gv,
    const float* __restrict__ geps, const float* __restrict__ gI,
    const float* __restrict__ gW,  const float* __restrict__ gsb,
    const float* __restrict__ gsn, const float* __restrict__ gd,
    const float* __restrict__ gr,  float* __restrict__ out)
{
    extern __shared__ float4 stab[];   // NODES float4 = 50 KB (dynamic)
    __shared__ float4 skn[KN];         // (C_nats, A'*IE, C*IE, B_nats)
    __shared__ float4 sint4[NPH];      // (a*IE, b*IE, a_nats, 0)
    __shared__ float  sRed[TPB / 32];
    __shared__ bool   s_last;

    const int tid  = threadIdx.x;
    const int wid  = tid >> 5;
    const int lane = tid & 31;
    const float IE  = 1.44269504088896340736f;  // log2(e)
    const float LN2 = 0.69314718055994530942f;

    // ---- preamble: every thread, all-MUFU ----
    const float sb  = gsb[0];
    const float sn  = gsn[0];
    const float dd  = gd[0];
    const float r0  = gr[0];
    const float rho = 1.0f - 2.0f * frcp(fex2(2.0f * r0 * IE) + 1.0f);  // tanh
    const float omr = 1.0f - rho;
    const float s2  = sn * sn * omr;
    const float isn2 = frcp(sn * sn);
    const float inv_s2 = frcp(s2);
    const float l2sn = flg2(sn);
    const float k_u = -0.5f * IE * isn2;
    const float k_v = -IE * inv_s2;

    float mw = gW[0];
    #pragma unroll
    for (int j = 1; j < NROWS; j++) mw = fmaxf(mw, gW[j]);
    float sw = 0.0f;
    #pragma unroll
    for (int j = 0; j < NROWS; j++) sw += fex2((gW[j] - mw) * IE);
    const float lse2 = mw * IE + flg2(sw);      // log2 sum exp W

    const float l2sr = l2sn + 0.5f * flg2(omr);
    const float cIn2 = IE * (0.69314718056f + 0.12078223764f
                             - 0.5f * 1.83787706641f)
                       - 3.0f * l2sr - l2sn;
    const float cCn2 = -(l2sn + l2sr + IE * (1.14472988585f + 0.34657359028f))
                       - 6.0f;                  // log2(64) = 6

    // ---- phase 0: (k,n) constants ----
    if (tid < KN) {
        const int IAc[NK] = {0,0,0,1,1,2};
        const int IBc[NK] = {1,2,3,2,3,3};
        int k = tid >> 6;
        float Ia = gI[IAc[k]];
        float Ib = gI[IBc[k]];
        float dI = Ib - Ia;
        float gc = dI * rsqrtf(2.0f * CUDART_PI_F * sb * sb);
        float x  = geps[tid] * (2.0f * dd * sb) - dd * sb;
        float z  = x * frcp(1.41421356237309515f * sb);
        float In = (erff(z) + 1.0f) * 0.5f * dI + Ia;
        float G  = gc * fex2(-z * z * IE);      // erfinv(erf(z)) == z
        float B  = In * isn2;
        float Ap2 = (-0.5f * In * In * isn2 - G * G * inv_s2) * IE
                    + cCn2 + (gW[NPH + k] * IE - lse2) - flg2(G);
        float C  = 2.0f * G * inv_s2;
        skn[tid] = make_float4(C, Ap2, C * IE, B);

        if (tid < NPH) {
            float Ip = gI[tid];
            float a = Ip * isn2;
            float b2 = -0.5f * Ip * Ip * isn2 * IE + cIn2
                       + (gW[tid] * IE - lse2);
            sint4[tid] = make_float4(a * IE, b2, a, 0.0f);
        }
    }
    __syncthreads();

    // ---- phase 1: build table in global (grid-split, <=1 node/warp) ----
    {
        int node = blockIdx.x * (TPB / 32) + wid;
        if (node < NODES) {
            int iu = node / NVN;
            int iv = node - iu * NVN;
            float u = iu * HUC;
            float v = V0C + iv * HVC;
            float inv_v = frcp(v);
            float uIE = u * IE;

            float sT = 0.f, sTu = 0.f, sTv = 0.f, sTuv = 0.f;
            #pragma unroll
            for (int t = 0; t < KN / 32; t++) {
                float4 c = skn[lane + (t << 5)];
                float qh  = fex2(fmaf(uIE, c.w, c.y));
                float xn  = c.z * v;
                float ex  = fex2(xn);
                float iex = frcp(ex);
                float sh  = ex - iex;
                float ch  = ex + iex;
                float tv  = fmaf(c.x, ch, -sh * inv_v);
                float qs = qh * sh;
                float qt = qh * tv;
                sT   += qs;
                sTv  += qt;
                sTu  = fmaf(qs, c.w, sTu);
                sTuv = fmaf(qt, c.w, sTuv);
            }
            #pragma unroll
            for (int o = 16; o; o >>= 1) {
                sT   += __shfl_xor_sync(0xffffffffu, sT,   o);
                sTu  += __shfl_xor_sync(0xffffffffu, sTu,  o);
                sTv  += __shfl_xor_sync(0xffffffffu, sTv,  o);
                sTuv += __shfl_xor_sync(0xffffffffu, sTuv, o);
            }
            if (lane == 0) {
                float T   = sT   * inv_v;
                float Tu  = sTu  * inv_v;
                float Tv  = sTv  * inv_v;
                float Tuv = sTuv * inv_v;
                #pragma unroll
                for (int p = 0; p < NPH; p++) {
                    float4 ab = sint4[p];
                    float tp = fex2(fmaf(u, ab.x, ab.y));
                    T  += tp;
                    Tu = fmaf(ab.z, tp, Tu);
                }
                float invT = frcp(T);
                float hu = Tu * invT;
                float hv = Tv * invT;
                float4 o;
                o.x = flg2(T);
                o.y = hu * IE;
                o.z = hv * IE;
                o.w = (Tuv * invT - hu * hv) * IE;
                g_table[node] = o;
            }
        }
    }

    // ---- prefetch first point's inputs BEFORE the grid barrier ----
    const int idx0 = blockIdx.x * TPB + tid;
    float u_pf = 0.5f, v_pf = 0.1f;
    if (idx0 < MDATA) {
        u_pf = __ldg(gu + idx0);
        v_pf = __ldg(gv + idx0);
    }

    // ---- device-wide barrier (456 co-resident blocks) ----
    if (tid == 0) {
        __threadfence();
        atomicAdd(&g_sync, 1u);
        while (ld_acq(&g_sync) < NBLK) __nanosleep(32);
    }
    __syncthreads();

    // ---- stage table to shared (coalesced) ----
    for (int i = tid; i < NODES; i += TPB) stab[i] = __ldg(g_table + i);
    __syncthreads();

    // ---- phase 2: grid-stride points, table from smem ----
    float acc = 0.0f;
    float u = u_pf, v = v_pf;
    for (int m = idx0; m < MDATA; m += NBLK * TPB) {
        float l2v = flg2(v);
        float pm = k_u * u * u + k_v * v * v + 2.0f * l2v;

        float su = u * (float)NUI;
        int iu = (int)su; iu = min(max(iu, 0), NUI - 1);
        float s = su - (float)iu;
        float sv = (v - V0C) * ((float)NVI / 0.3f);
        int iv = (int)sv; iv = min(max(iv, 0), NVI - 1);
        float t = sv - (float)iv;

        const float4* tb = stab + (iu * NVN + iv);
        float4 c00 = tb[0];
        float4 c01 = tb[1];
        float4 c10 = tb[NVN];
        float4 c11 = tb[NVN + 1];

        // next point's u/v (overlap load with math)
        int mn = m + NBLK * TPB;
        if (mn < MDATA) { u = __ldg(gu + mn); v = __ldg(gv + mn); }

        float ss = s * s, s3 = ss * s;
        float Au0 = 2.0f * s3 - 3.0f * ss + 1.0f;
        float Au1 = (s3 - 2.0f * ss + s) * HUC;
        float Au2 = 3.0f * ss - 2.0f * s3;
        float Au3 = (s3 - ss) * HUC;
        float tt = t * t, t3 = tt * t;
        float Av0 = 2.0f * t3 - 3.0f * tt + 1.0f;
        float Av1 = (t3 - 2.0f * tt + t) * HVC;
        float Av2 = 3.0f * tt - 2.0f * t3;
        float Av3 = (t3 - tt) * HVC;

        float P0 = Av0*c00.x + Av1*c00.z + Av2*c01.x + Av3*c01.z;
        float P1 = Av0*c00.y + Av1*c00.w + Av2*c01.y + Av3*c01.w;
        float P2 = Av0*c10.x + Av1*c10.z + Av2*c11.x + Av3*c11.z;
        float P3 = Av0*c10.y + Av1*c10.w + Av2*c11.y + Av3*c11.w;
        float f  = Au0*P0 + Au1*P1 + Au2*P2 + Au3*P3;

        acc += pm + f;
    }

    // ---- deterministic block + grid reduction ----
    #pragma unroll
    for (int o = 16; o > 0; o >>= 1) acc += __shfl_down_sync(0xffffffffu, acc, o);
    if (lane == 0) sRed[wid] = acc;
    __syncthreads();
    if (tid == 0) {
        float bs = 0.0f;
        #pragma unroll
        for (int w = 0; w < TPB / 32; w++) bs += sRed[w];
        g_partials[blockIdx.x] = bs;
        __threadfence();
        unsigned int ticket = atomicAdd(&g_count, 1u);
        s_last = (ticket == NBLK - 1);
    }
    __syncthreads();

    if (s_last) {
        float a = 0.0f;
        if (tid < 32) {
            for (int i = tid; i < NBLK; i += 32) a += g_partials[i];
            #pragma unroll
            for (int o = 16; o > 0; o >>= 1) a += __shfl_down_sync(0xffffffffu, a, o);
            if (tid == 0) {
                out[0] = -a * (LN2 / (float)MDATA);
                g_sync  = 0;   // reset for next graph replay
                g_count = 0;
            }
        }
    }
}

extern "C" void kernel_launch(void* const* d_in, const int* in_sizes, int n_in,
                              void* d_out, int out_size) {
    (void)in_sizes; (void)n_in; (void)out_size;

    static bool attr_done = false;
    if (!attr_done) {
        cudaFuncSetAttribute(bimm_fused_kernel,
                             cudaFuncAttributeMaxDynamicSharedMemorySize,
                             NODES * (int)sizeof(float4));
        attr_done = true;
    }

    bimm_fused_kernel<<<NBLK, TPB, NODES * sizeof(float4)>>>(
        (const float*)d_in[0], (const float*)d_in[1], (const float*)d_in[2],
        (const float*)d_in[3], (const float*)d_in[4], (const float*)d_in[5],
        (const float*)d_in[6], (const float*)d_in[7], (const float*)d_in[8],
        (float*)d_out);
}

// round 11
// speedup vs baseline: 1.1233x; 1.1233x over previous
#include <cuda_runtime.h>
#include <math_constants.h>

#define MDATA 250000
#define NPH 4
#define NK 6
#define NMC 64
#define KN (NK*NMC)            // 384
#define NROWS (NPH+NK)

#define NUI 96
#define NVI 32
#define NUN (NUI+1)            // 97
#define NVN (NVI+1)            // 33
#define NODES (NUN*NVN)        // 3201 -> 50 KB table (L2-resident)

#define V0C 0.01f
#define HUC (1.0f/96.0f)
#define HVC (0.3f/32.0f)

#define TPB 512
#define OCC 2
#define NBLK (152*OCC)         // 304 blocks, 2/SM, all co-resident

__device__ float4 g_table[NODES];
__device__ float  g_partials[NBLK];
__device__ unsigned int g_sync  = 0;
__device__ unsigned int g_count = 0;

__device__ __forceinline__ float fex2(float x) {
    float y; asm("ex2.approx.ftz.f32 %0, %1;" : "=f"(y) : "f"(x)); return y;
}
__device__ __forceinline__ float flg2(float x) {
    float y; asm("lg2.approx.ftz.f32 %0, %1;" : "=f"(y) : "f"(x)); return y;
}
__device__ __forceinline__ float frcp(float x) {
    float y; asm("rcp.approx.ftz.f32 %0, %1;" : "=f"(y) : "f"(x)); return y;
}
__device__ __forceinline__ unsigned int ld_acq(const unsigned int* p) {
    unsigned int v;
    asm volatile("ld.global.acquire.gpu.u32 %0, [%1];" : "=r"(v) : "l"(p));
    return v;
}

__global__ void __launch_bounds__(TPB, OCC) bimm_fused_kernel(
    const float* __restrict__ gu, const float* __restrict__ gv,
    const float* __restrict__ geps, const float* __restrict__ gI,
    const float* __restrict__ gW,  const float* __restrict__ gsb,
    const float* __restrict__ gsn, const float* __restrict__ gd,
    const float* __restrict__ gr,  float* __restrict__ out)
{
    __shared__ float4 skn[KN];         // (C_nats, A'*IE, C*IE, B_nats)
    __shared__ float4 sint4[NPH];      // (a*IE, b*IE, a_nats, 0)
    __shared__ float  sRed[TPB / 32];
    __shared__ bool   s_last;

    const int tid  = threadIdx.x;
    const int wid  = tid >> 5;
    const int lane = tid & 31;
    const float IE  = 1.44269504088896340736f;  // log2(e)
    const float LN2 = 0.69314718055994530942f;

    // ---- issue the phase-2 data loads FIRST (longest latency) ----
    const int idx = blockIdx.x * TPB + tid;     // pair index
    const bool havept = (idx * 2 < MDATA);      // MDATA even: full pairs only
    float2 u2 = make_float2(0.5f, 0.5f);
    float2 v2 = make_float2(0.1f, 0.1f);
    if (havept) {
        u2 = __ldg((const float2*)gu + idx);
        v2 = __ldg((const float2*)gv + idx);
    }

    // ---- preamble: every thread, all-MUFU ----
    const float sb  = gsb[0];
    const float sn  = gsn[0];
    const float dd  = gd[0];
    const float r0  = gr[0];
    const float rho = 1.0f - 2.0f * frcp(fex2(2.0f * r0 * IE) + 1.0f);  // tanh
    const float omr = 1.0f - rho;
    const float s2  = sn * sn * omr;
    const float isn2 = frcp(sn * sn);
    const float inv_s2 = frcp(s2);
    const float l2sn = flg2(sn);
    const float k_u = -0.5f * IE * isn2;
    const float k_v = -IE * inv_s2;

    float mw = gW[0];
    #pragma unroll
    for (int j = 1; j < NROWS; j++) mw = fmaxf(mw, gW[j]);
    float sw = 0.0f;
    #pragma unroll
    for (int j = 0; j < NROWS; j++) sw += fex2((gW[j] - mw) * IE);
    const float lse2 = mw * IE + flg2(sw);      // log2 sum exp W

    const float l2sr = l2sn + 0.5f * flg2(omr);
    const float cIn2 = IE * (0.69314718056f + 0.12078223764f
                             - 0.5f * 1.83787706641f)
                       - 3.0f * l2sr - l2sn;
    const float cCn2 = -(l2sn + l2sr + IE * (1.14472988585f + 0.34657359028f))
                       - 6.0f;                  // log2(64) = 6

    // ---- phase 0: (k,n) constants ----
    if (tid < KN) {
        const int IAc[NK] = {0,0,0,1,1,2};
        const int IBc[NK] = {1,2,3,2,3,3};
        int k = tid >> 6;
        float Ia = gI[IAc[k]];
        float Ib = gI[IBc[k]];
        float dI = Ib - Ia;
        float gc = dI * rsqrtf(2.0f * CUDART_PI_F * sb * sb);
        float x  = geps[tid] * (2.0f * dd * sb) - dd * sb;
        float z  = x * frcp(1.41421356237309515f * sb);
        float In = (erff(z) + 1.0f) * 0.5f * dI + Ia;
        float G  = gc * fex2(-z * z * IE);      // erfinv(erf(z)) == z
        float B  = In * isn2;
        float Ap2 = (-0.5f * In * In * isn2 - G * G * inv_s2) * IE
                    + cCn2 + (gW[NPH + k] * IE - lse2) - flg2(G);
        float C  = 2.0f * G * inv_s2;
        skn[tid] = make_float4(C, Ap2, C * IE, B);

        if (tid < NPH) {
            float Ip = gI[tid];
            float a = Ip * isn2;
            float b2 = -0.5f * Ip * Ip * isn2 * IE + cIn2
                       + (gW[tid] * IE - lse2);
            sint4[tid] = make_float4(a * IE, b2, a, 0.0f);
        }
    }
    __syncthreads();

    // ---- phase 1: build table in global (grid-split, <=1 node/warp) ----
    {
        int node = blockIdx.x * (TPB / 32) + wid;
        if (node < NODES) {
            int iu = node / NVN;
            int iv = node - iu * NVN;
            float u = iu * HUC;
            float v = V0C + iv * HVC;
            float inv_v = frcp(v);
            float uIE = u * IE;

            float sT = 0.f, sTu = 0.f, sTv = 0.f, sTuv = 0.f;
            #pragma unroll
            for (int t = 0; t < KN / 32; t++) {
                float4 c = skn[lane + (t << 5)];
                float qh  = fex2(fmaf(uIE, c.w, c.y));
                float xn  = c.z * v;
                float ex  = fex2(xn);
                float iex = frcp(ex);
                float sh  = ex - iex;
                float ch  = ex + iex;
                float tv  = fmaf(c.x, ch, -sh * inv_v);
                float qs = qh * sh;
                float qt = qh * tv;
                sT   += qs;
                sTv  += qt;
                sTu  = fmaf(qs, c.w, sTu);
                sTuv = fmaf(qt, c.w, sTuv);
            }
            #pragma unroll
            for (int o = 16; o; o >>= 1) {
                sT   += __shfl_xor_sync(0xffffffffu, sT,   o);
                sTu  += __shfl_xor_sync(0xffffffffu, sTu,  o);
                sTv  += __shfl_xor_sync(0xffffffffu, sTv,  o);
                sTuv += __shfl_xor_sync(0xffffffffu, sTuv, o);
            }
            if (lane == 0) {
                float T   = sT   * inv_v;
                float Tu  = sTu  * inv_v;
                float Tv  = sTv  * inv_v;
                float Tuv = sTuv * inv_v;
                #pragma unroll
                for (int p = 0; p < NPH; p++) {
                    float4 ab = sint4[p];
                    float tp = fex2(fmaf(u, ab.x, ab.y));
                    T  += tp;
                    Tu = fmaf(ab.z, tp, Tu);
                }
                float invT = frcp(T);
                float hu = Tu * invT;
                float hv = Tv * invT;
                float4 o;
                o.x = flg2(T);
                o.y = hu * IE;
                o.z = hv * IE;
                o.w = (Tuv * invT - hu * hv) * IE;
                g_table[node] = o;
            }
        }
    }

    // ---- pre-barrier: ALL phase-2 prep (pm, cells, Hermite bases) ----
    float pmv[2];
    int   baseA[2];
    float AuB[2][4], AvB[2][4];
    #pragma unroll
    for (int i = 0; i < 2; i++) {
        float u = (i == 0) ? u2.x : u2.y;
        float v = (i == 0) ? v2.x : v2.y;
        float l2v = flg2(v);
        pmv[i] = k_u * u * u + k_v * v * v + 2.0f * l2v;

        float su = u * (float)NUI;
        int iu = (int)su; iu = min(max(iu, 0), NUI - 1);
        float s = su - (float)iu;
        float sv = (v - V0C) * ((float)NVI / 0.3f);
        int iv = (int)sv; iv = min(max(iv, 0), NVI - 1);
        float t = sv - (float)iv;
        baseA[i] = iu * NVN + iv;

        float ss = s * s, s3 = ss * s;
        AuB[i][0] = 2.0f * s3 - 3.0f * ss + 1.0f;
        AuB[i][1] = (s3 - 2.0f * ss + s) * HUC;
        AuB[i][2] = 3.0f * ss - 2.0f * s3;
        AuB[i][3] = (s3 - ss) * HUC;
        float tt = t * t, t3 = tt * t;
        AvB[i][0] = 2.0f * t3 - 3.0f * tt + 1.0f;
        AvB[i][1] = (t3 - 2.0f * tt + t) * HVC;
        AvB[i][2] = 3.0f * tt - 2.0f * t3;
        AvB[i][3] = (t3 - tt) * HVC;
    }

    // ---- device-wide barrier (304 co-resident blocks) ----
    if (tid == 0) {
        __threadfence();
        atomicAdd(&g_sync, 1u);
        while (ld_acq(&g_sync) < NBLK) __nanosleep(32);
    }
    __syncthreads();

    // ---- phase 2: only table reads + dot products remain ----
    float acc = 0.0f;
    if (havept) {
        #pragma unroll
        for (int i = 0; i < 2; i++) {
            const float4* tb = g_table + baseA[i];
            float4 c00 = __ldg(tb);
            float4 c01 = __ldg(tb + 1);
            float4 c10 = __ldg(tb + NVN);
            float4 c11 = __ldg(tb + NVN + 1);

            float Av0 = AvB[i][0], Av1 = AvB[i][1];
            float Av2 = AvB[i][2], Av3 = AvB[i][3];
            float P0 = Av0*c00.x + Av1*c00.z + Av2*c01.x + Av3*c01.z;
            float P1 = Av0*c00.y + Av1*c00.w + Av2*c01.y + Av3*c01.w;
            float P2 = Av0*c10.x + Av1*c10.z + Av2*c11.x + Av3*c11.z;
            float P3 = Av0*c10.y + Av1*c10.w + Av2*c11.y + Av3*c11.w;
            float f  = AuB[i][0]*P0 + AuB[i][1]*P1
                     + AuB[i][2]*P2 + AuB[i][3]*P3;

            acc += pmv[i] + f;
        }
    }

    // ---- deterministic block + grid reduction ----
    #pragma unroll
    for (int o = 16; o > 0; o >>= 1) acc += __shfl_down_sync(0xffffffffu, acc, o);
    if (lane == 0) sRed[wid] = acc;
    __syncthreads();
    if (tid == 0) {
        float bs = 0.0f;
        #pragma unroll
        for (int w = 0; w < TPB / 32; w++) bs += sRed[w];
        g_partials[blockIdx.x] = bs;
        __threadfence();
        unsigned int ticket = atomicAdd(&g_count, 1u);
        s_last = (ticket == NBLK - 1);
    }
    __syncthreads();

    if (s_last) {
        float a = 0.0f;
        if (tid < 32) {
            for (int i = tid; i < NBLK; i += 32) a += g_partials[i];
            #pragma unroll
            for (int o = 16; o > 0; o >>= 1) a += __shfl_down_sync(0xffffffffu, a, o);
            if (tid == 0) {
                out[0] = -a * (LN2 / (float)MDATA);
                g_sync  = 0;   // reset for next graph replay
                g_count = 0;
            }
        }
    }
}

extern "C" void kernel_launch(void* const* d_in, const int* in_sizes, int n_in,
                              void* d_out, int out_size) {
    (void)in_sizes; (void)n_in; (void)out_size;
    bimm_fused_kernel<<<NBLK, TPB>>>(
        (const float*)d_in[0], (const float*)d_in[1], (const float*)d_in[2],
        (const float*)d_in[3], (const float*)d_in[4], (const float*)d_in[5],
        (const float*)d_in[6], (const float*)d_in[7], (const float*)d_in[8],
        (float*)d_out);
}

// round 12
// speedup vs baseline: 1.1473x; 1.0213x over previous
#include <cuda_runtime.h>
#include <math_constants.h>

#define MDATA 250000
#define NPH 4
#define NK 6
#define NMC 64
#define KN (NK*NMC)            // 384
#define NROWS (NPH+NK)

#define NUI 64
#define NVI 24
#define NUN (NUI+1)            // 65
#define NVN (NVI+1)            // 25
#define NODES (NUN*NVN)        // 1625 -> 26 KB table (L2-resident)

#define V0C 0.01f
#define HUC (1.0f/64.0f)
#define HVC (0.3f/24.0f)

#define TPB 512
#define OCC 2
#define NBLK (152*OCC)         // 304 blocks, 2/SM, all co-resident
#define BW 6                   // builder warps per block (6*271 >= 1625)

__device__ float4 g_table[NODES];
__device__ float  g_partials[NBLK];
__device__ unsigned int g_sync  = 0;
__device__ unsigned int g_count = 0;

__device__ __forceinline__ float fex2(float x) {
    float y; asm("ex2.approx.ftz.f32 %0, %1;" : "=f"(y) : "f"(x)); return y;
}
__device__ __forceinline__ float flg2(float x) {
    float y; asm("lg2.approx.ftz.f32 %0, %1;" : "=f"(y) : "f"(x)); return y;
}
__device__ __forceinline__ float frcp(float x) {
    float y; asm("rcp.approx.ftz.f32 %0, %1;" : "=f"(y) : "f"(x)); return y;
}
__device__ __forceinline__ unsigned int ld_acq(const unsigned int* p) {
    unsigned int v;
    asm volatile("ld.global.acquire.gpu.u32 %0, [%1];" : "=r"(v) : "l"(p));
    return v;
}

__global__ void __launch_bounds__(TPB, OCC) bimm_fused_kernel(
    const float* __restrict__ gu, const float* __restrict__ gv,
    const float* __restrict__ geps, const float* __restrict__ gI,
    const float* __restrict__ gW,  const float* __restrict__ gsb,
    const float* __restrict__ gsn, const float* __restrict__ gd,
    const float* __restrict__ gr,  float* __restrict__ out)
{
    __shared__ float4 skn[KN];         // (C_nats, A'*IE, C*IE, B_nats)
    __shared__ float4 sint4[NPH];      // (a*IE, b*IE, a_nats, 0)
    __shared__ float  sRed[TPB / 32];
    __shared__ bool   s_last;

    const int tid  = threadIdx.x;
    const int wid  = tid >> 5;
    const int lane = tid & 31;
    const float IE  = 1.44269504088896340736f;  // log2(e)
    const float LN2 = 0.69314718055994530942f;

    // ---- issue the phase-2 data loads FIRST (longest latency) ----
    const int idx = blockIdx.x * TPB + tid;     // pair index
    const bool havept = (idx * 2 < MDATA);
    float2 u2 = make_float2(0.5f, 0.5f);
    float2 v2 = make_float2(0.1f, 0.1f);
    if (havept) {
        u2 = __ldg((const float2*)gu + idx);
        v2 = __ldg((const float2*)gv + idx);
    }

    // ---- preamble: every thread, all-MUFU, single-pass loads ----
    const float sb  = gsb[0];
    const float sn  = gsn[0];
    const float dd  = gd[0];
    const float r0  = gr[0];
    const float rho = 1.0f - 2.0f * frcp(fex2(2.0f * r0 * IE) + 1.0f);  // tanh
    const float omr = 1.0f - rho;
    const float s2  = sn * sn * omr;
    const float isn2 = frcp(sn * sn);
    const float inv_s2 = frcp(s2);
    const float l2sn = flg2(sn);
    const float k_u = -0.5f * IE * isn2;
    const float k_v = -IE * inv_s2;

    // log-softmax normalizer: load once, tree max, then sum
    float w0 = gW[0], w1 = gW[1], w2 = gW[2], w3 = gW[3], w4 = gW[4];
    float w5 = gW[5], w6 = gW[6], w7 = gW[7], w8 = gW[8], w9 = gW[9];
    float mA = fmaxf(fmaxf(fmaxf(w0, w1), fmaxf(w2, w3)),
                     fmaxf(fmaxf(w4, w5), fmaxf(w6, w7)));
    float mw = fmaxf(mA, fmaxf(w8, w9));
    float sw = fex2((w0 - mw) * IE) + fex2((w1 - mw) * IE)
             + fex2((w2 - mw) * IE) + fex2((w3 - mw) * IE)
             + fex2((w4 - mw) * IE) + fex2((w5 - mw) * IE)
             + fex2((w6 - mw) * IE) + fex2((w7 - mw) * IE)
             + fex2((w8 - mw) * IE) + fex2((w9 - mw) * IE);
    const float lse2 = mw * IE + flg2(sw);      // log2 sum exp W

    const float l2sr = l2sn + 0.5f * flg2(omr);
    const float cIn2 = IE * (0.69314718056f + 0.12078223764f
                             - 0.5f * 1.83787706641f)
                       - 3.0f * l2sr - l2sn;
    const float cCn2 = -(l2sn + l2sr + IE * (1.14472988585f + 0.34657359028f))
                       - 6.0f;                  // log2(64) = 6

    // ---- phase 0: (k,n) constants ----
    if (tid < KN) {
        const int IAc[NK] = {0,0,0,1,1,2};
        const int IBc[NK] = {1,2,3,2,3,3};
        int k = tid >> 6;
        float Ia = gI[IAc[k]];
        float Ib = gI[IBc[k]];
        float dI = Ib - Ia;
        float gc = dI * rsqrtf(2.0f * CUDART_PI_F * sb * sb);
        float x  = geps[tid] * (2.0f * dd * sb) - dd * sb;
        float z  = x * frcp(1.41421356237309515f * sb);
        float In = (erff(z) + 1.0f) * 0.5f * dI + Ia;
        float G  = gc * fex2(-z * z * IE);      // erfinv(erf(z)) == z
        float B  = In * isn2;
        float wk = (k < 2) ? ((k == 0) ? w4 : w5)
                           : ((k == 2) ? w6 : (k == 3) ? w7 : (k == 4) ? w8 : w9);
        float Ap2 = (-0.5f * In * In * isn2 - G * G * inv_s2) * IE
                    + cCn2 + (wk * IE - lse2) - flg2(G);
        float C  = 2.0f * G * inv_s2;
        skn[tid] = make_float4(C, Ap2, C * IE, B);

        if (tid < NPH) {
            float Ip = gI[tid];
            float wp = (tid == 0) ? w0 : (tid == 1) ? w1 : (tid == 2) ? w2 : w3;
            float a = Ip * isn2;
            float b2 = -0.5f * Ip * Ip * isn2 * IE + cIn2
                       + (wp * IE - lse2);
            sint4[tid] = make_float4(a * IE, b2, a, 0.0f);
        }
    }
    __syncthreads();

    // ---- phase 1: build table (BW builder warps per block) ----
    if (wid < BW) {
        int node = blockIdx.x * BW + wid;
        if (node < NODES) {
            int iu = node / NVN;
            int iv = node - iu * NVN;
            float u = iu * HUC;
            float v = V0C + iv * HVC;
            float inv_v = frcp(v);
            float uIE = u * IE;

            float sT = 0.f, sTu = 0.f, sTv = 0.f, sTuv = 0.f;
            #pragma unroll
            for (int t = 0; t < KN / 32; t++) {
                float4 c = skn[lane + (t << 5)];
                float e1 = fmaf(uIE, c.w, c.y);
                float xn = c.z * v;
                float p  = fex2(e1 + xn);       // qh * exp(Cv)
                float m  = fex2(e1 - xn);       // qh * exp(-Cv)
                float qs = p - m;               // qh * 2sinh(Cv)
                float qc = p + m;               // qh * 2cosh(Cv)
                float qt = fmaf(c.x, qc, -qs * inv_v);
                sT   += qs;
                sTv  += qt;
                sTu  = fmaf(qs, c.w, sTu);
                sTuv = fmaf(qt, c.w, sTuv);
            }
            #pragma unroll
            for (int o = 16; o; o >>= 1) {
                sT   += __shfl_xor_sync(0xffffffffu, sT,   o);
                sTu  += __shfl_xor_sync(0xffffffffu, sTu,  o);
                sTv  += __shfl_xor_sync(0xffffffffu, sTv,  o);
                sTuv += __shfl_xor_sync(0xffffffffu, sTuv, o);
            }
            if (lane == 0) {
                float T   = sT   * inv_v;
                float Tu  = sTu  * inv_v;
                float Tv  = sTv  * inv_v;
                float Tuv = sTuv * inv_v;
                #pragma unroll
                for (int p2 = 0; p2 < NPH; p2++) {
                    float4 ab = sint4[p2];
                    float tp = fex2(fmaf(u, ab.x, ab.y));
                    T  += tp;
                    Tu = fmaf(ab.z, tp, Tu);
                }
                float invT = frcp(T);
                float hu = Tu * invT;
                float hv = Tv * invT;
                float4 o;
                o.x = flg2(T);
                o.y = hu * IE;
                o.z = hv * IE;
                o.w = (Tuv * invT - hu * hv) * IE;
                g_table[node] = o;
            }
        }
    }

    // ---- pre-barrier: ALL phase-2 prep (pm, cells, Hermite bases) ----
    float pmv[2];
    int   baseA[2];
    float AuB[2][4], AvB[2][4];
    #pragma unroll
    for (int i = 0; i < 2; i++) {
        float u = (i == 0) ? u2.x : u2.y;
        float v = (i == 0) ? v2.x : v2.y;
        float l2v = flg2(v);
        pmv[i] = k_u * u * u + k_v * v * v + 2.0f * l2v;

        float su = u * (float)NUI;
        int iu = (int)su; iu = min(max(iu, 0), NUI - 1);
        float s = su - (float)iu;
        float sv = (v - V0C) * ((float)NVI / 0.3f);
        int iv = (int)sv; iv = min(max(iv, 0), NVI - 1);
        float t = sv - (float)iv;
        baseA[i] = iu * NVN + iv;

        float ss = s * s, s3 = ss * s;
        AuB[i][0] = 2.0f * s3 - 3.0f * ss + 1.0f;
        AuB[i][1] = (s3 - 2.0f * ss + s) * HUC;
        AuB[i][2] = 3.0f * ss - 2.0f * s3;
        AuB[i][3] = (s3 - ss) * HUC;
        float tt = t * t, t3 = tt * t;
        AvB[i][0] = 2.0f * t3 - 3.0f * tt + 1.0f;
        AvB[i][1] = (t3 - 2.0f * tt + t) * HVC;
        AvB[i][2] = 3.0f * tt - 2.0f * t3;
        AvB[i][3] = (t3 - tt) * HVC;
    }

    // ---- device-wide barrier (304 co-resident blocks) ----
    if (tid == 0) {
        __threadfence();
        atomicAdd(&g_sync, 1u);
        while (ld_acq(&g_sync) < NBLK) __nanosleep(32);
    }
    __syncthreads();

    // ---- phase 2: only table reads + dot products remain ----
    float acc = 0.0f;
    if (havept) {
        #pragma unroll
        for (int i = 0; i < 2; i++) {
            const float4* tb = g_table + baseA[i];
            float4 c00 = __ldg(tb);
            float4 c01 = __ldg(tb + 1);
            float4 c10 = __ldg(tb + NVN);
            float4 c11 = __ldg(tb + NVN + 1);

            float Av0 = AvB[i][0], Av1 = AvB[i][1];
            float Av2 = AvB[i][2], Av3 = AvB[i][3];
            float P0 = Av0*c00.x + Av1*c00.z + Av2*c01.x + Av3*c01.z;
            float P1 = Av0*c00.y + Av1*c00.w + Av2*c01.y + Av3*c01.w;
            float P2 = Av0*c10.x + Av1*c10.z + Av2*c11.x + Av3*c11.z;
            float P3 = Av0*c10.y + Av1*c10.w + Av2*c11.y + Av3*c11.w;
            float f  = AuB[i][0]*P0 + AuB[i][1]*P1
                     + AuB[i][2]*P2 + AuB[i][3]*P3;

            acc += pmv[i] + f;
        }
    }

    // ---- deterministic block + grid reduction ----
    #pragma unroll
    for (int o = 16; o > 0; o >>= 1) acc += __shfl_down_sync(0xffffffffu, acc, o);
    if (lane == 0) sRed[wid] = acc;
    __syncthreads();
    if (tid == 0) {
        float bs = 0.0f;
        #pragma unroll
        for (int w = 0; w < TPB / 32; w++) bs += sRed[w];
        g_partials[blockIdx.x] = bs;
        __threadfence();
        unsigned int ticket = atomicAdd(&g_count, 1u);
        s_last = (ticket == NBLK - 1);
    }
    __syncthreads();

    if (s_last) {
        float a = 0.0f;
        if (tid < 32) {
            for (int i = tid; i < NBLK; i += 32) a += g_partials[i];
            #pragma unroll
            for (int o = 16; o > 0; o >>= 1) a += __shfl_down_sync(0xffffffffu, a, o);
            if (tid == 0) {
                out[0] = -a * (LN2 / (float)MDATA);
                g_sync  = 0;   // reset for next graph replay
                g_count = 0;
            }
        }
    }
}

extern "C" void kernel_launch(void* const* d_in, const int* in_sizes, int n_in,
                              void* d_out, int out_size) {
    (void)in_sizes; (void)n_in; (void)out_size;
    bimm_fused_kernel<<<NBLK, TPB>>>(
        (const float*)d_in[0], (const float*)d_in[1], (const float*)d_in[2],
        (const float*)d_in[3], (const float*)d_in[4], (const float*)d_in[5],
        (const float*)d_in[6], (const float*)d_in[7], (const float*)d_in[8],
        (float*)d_out);
}

// round 13
// speedup vs baseline: 1.4545x; 1.2678x over previous
#include <cuda_runtime.h>
#include <math_constants.h>

#define MDATA 250000
#define NPH 4
#define NK 6
#define NMC 64
#define KN (NK*NMC)            // 384
#define NROWS (NPH+NK)

#define NUI 64
#define NVI 24
#define NUN (NUI+1)            // 65
#define NVN (NVI+1)            // 25
#define NODES (NUN*NVN)        // 1625 -> 26 KB table (L2-resident)

#define V0C 0.01f
#define HUC (1.0f/64.0f)
#define HVC (0.3f/24.0f)

#define TPB 512
#define OCC 2
#define NBLK (152*OCC)         // 304 blocks, 2/SM, all co-resident
#define BW 6                   // builder warps per block (6*271 >= 1625)

__device__ float4 g_table[NODES];
__device__ float  g_accum = 0.0f;
__device__ unsigned int g_sync  = 0;
__device__ unsigned int g_count = 0;

__device__ __forceinline__ float fex2(float x) {
    float y; asm("ex2.approx.ftz.f32 %0, %1;" : "=f"(y) : "f"(x)); return y;
}
__device__ __forceinline__ float flg2(float x) {
    float y; asm("lg2.approx.ftz.f32 %0, %1;" : "=f"(y) : "f"(x)); return y;
}
__device__ __forceinline__ float frcp(float x) {
    float y; asm("rcp.approx.ftz.f32 %0, %1;" : "=f"(y) : "f"(x)); return y;
}
__device__ __forceinline__ unsigned int ld_acq(const unsigned int* p) {
    unsigned int v;
    asm volatile("ld.global.acquire.gpu.u32 %0, [%1];" : "=r"(v) : "l"(p));
    return v;
}

__global__ void __launch_bounds__(TPB, OCC) bimm_fused_kernel(
    const float* __restrict__ gu, const float* __restrict__ gv,
    const float* __restrict__ geps, const float* __restrict__ gI,
    const float* __restrict__ gW,  const float* __restrict__ gsb,
    const float* __restrict__ gsn, const float* __restrict__ gd,
    const float* __restrict__ gr,  float* __restrict__ out)
{
    __shared__ float4 skn[KN];         // (C_nats, A'*IE, C*IE, B_nats)
    __shared__ float4 sint4[NPH];      // (a*IE, b*IE, a_nats, 0)
    __shared__ float  sRed[TPB / 32];
    __shared__ bool   s_last;

    const int tid  = threadIdx.x;
    const int wid  = tid >> 5;
    const int lane = tid & 31;
    const float IE  = 1.44269504088896340736f;  // log2(e)
    const float LN2 = 0.69314718055994530942f;

    // ---- issue the phase-2 data loads FIRST (longest latency) ----
    const int idx = blockIdx.x * TPB + tid;     // pair index
    const bool havept = (idx * 2 < MDATA);
    float2 u2 = make_float2(0.5f, 0.5f);
    float2 v2 = make_float2(0.1f, 0.1f);
    if (havept) {
        u2 = __ldg((const float2*)gu + idx);
        v2 = __ldg((const float2*)gv + idx);
    }

    // ---- preamble: every thread, all-MUFU, single-pass loads ----
    const float sb  = gsb[0];
    const float sn  = gsn[0];
    const float dd  = gd[0];
    const float r0  = gr[0];
    const float rho = 1.0f - 2.0f * frcp(fex2(2.0f * r0 * IE) + 1.0f);  // tanh
    const float omr = 1.0f - rho;
    const float s2  = sn * sn * omr;
    const float isn2 = frcp(sn * sn);
    const float inv_s2 = frcp(s2);
    const float l2sn = flg2(sn);
    const float k_u = -0.5f * IE * isn2;        // coeff of u^2 (log2) -> folded
    const float k_v = -IE * inv_s2;             // coeff of v^2 (log2) -> folded

    // log-softmax normalizer: load once, tree max, then sum
    float w0 = gW[0], w1 = gW[1], w2 = gW[2], w3 = gW[3], w4 = gW[4];
    float w5 = gW[5], w6 = gW[6], w7 = gW[7], w8 = gW[8], w9 = gW[9];
    float mA = fmaxf(fmaxf(fmaxf(w0, w1), fmaxf(w2, w3)),
                     fmaxf(fmaxf(w4, w5), fmaxf(w6, w7)));
    float mw = fmaxf(mA, fmaxf(w8, w9));
    float sw = fex2((w0 - mw) * IE) + fex2((w1 - mw) * IE)
             + fex2((w2 - mw) * IE) + fex2((w3 - mw) * IE)
             + fex2((w4 - mw) * IE) + fex2((w5 - mw) * IE)
             + fex2((w6 - mw) * IE) + fex2((w7 - mw) * IE)
             + fex2((w8 - mw) * IE) + fex2((w9 - mw) * IE);
    const float lse2 = mw * IE + flg2(sw);      // log2 sum exp W

    const float l2sr = l2sn + 0.5f * flg2(omr);
    const float cIn2 = IE * (0.69314718056f + 0.12078223764f
                             - 0.5f * 1.83787706641f)
                       - 3.0f * l2sr - l2sn;
    const float cCn2 = -(l2sn + l2sr + IE * (1.14472988585f + 0.34657359028f))
                       - 6.0f;                  // log2(64) = 6

    // ---- phase 0: (k,n) constants ----
    if (tid < KN) {
        const int IAc[NK] = {0,0,0,1,1,2};
        const int IBc[NK] = {1,2,3,2,3,3};
        int k = tid >> 6;
        float Ia = gI[IAc[k]];
        float Ib = gI[IBc[k]];
        float dI = Ib - Ia;
        float gc = dI * rsqrtf(2.0f * CUDART_PI_F * sb * sb);
        float x  = geps[tid] * (2.0f * dd * sb) - dd * sb;
        float z  = x * frcp(1.41421356237309515f * sb);
        float In = (erff(z) + 1.0f) * 0.5f * dI + Ia;
        float G  = gc * fex2(-z * z * IE);      // erfinv(erf(z)) == z
        float B  = In * isn2;
        float wk = (k < 2) ? ((k == 0) ? w4 : w5)
                           : ((k == 2) ? w6 : (k == 3) ? w7 : (k == 4) ? w8 : w9);
        float Ap2 = (-0.5f * In * In * isn2 - G * G * inv_s2) * IE
                    + cCn2 + (wk * IE - lse2) - flg2(G);
        float C  = 2.0f * G * inv_s2;
        skn[tid] = make_float4(C, Ap2, C * IE, B);

        if (tid < NPH) {
            float Ip = gI[tid];
            float wp = (tid == 0) ? w0 : (tid == 1) ? w1 : (tid == 2) ? w2 : w3;
            float a = Ip * isn2;
            float b2 = -0.5f * Ip * Ip * isn2 * IE + cIn2
                       + (wp * IE - lse2);
            sint4[tid] = make_float4(a * IE, b2, a, 0.0f);
        }
    }
    __syncthreads();

    // ---- phase 1: build table (BW builder warps per block) ----
    // Table now stores H(u,v) + k_u*u^2 + k_v*v^2 (exact fold: quadratics
    // are represented exactly by bicubic Hermite).
    if (wid < BW) {
        int node = blockIdx.x * BW + wid;
        if (node < NODES) {
            int iu = node / NVN;
            int iv = node - iu * NVN;
            float u = iu * HUC;
            float v = V0C + iv * HVC;
            float inv_v = frcp(v);
            float uIE = u * IE;

            float sT = 0.f, sTu = 0.f, sTv = 0.f, sTuv = 0.f;
            #pragma unroll
            for (int t = 0; t < KN / 32; t++) {
                float4 c = skn[lane + (t << 5)];
                float e1 = fmaf(uIE, c.w, c.y);
                float xn = c.z * v;
                float p  = fex2(e1 + xn);       // qh * exp(Cv)
                float m  = fex2(e1 - xn);       // qh * exp(-Cv)
                float qs = p - m;               // qh * 2sinh(Cv)
                float qc = p + m;               // qh * 2cosh(Cv)
                float qt = fmaf(c.x, qc, -qs * inv_v);
                sT   += qs;
                sTv  += qt;
                sTu  = fmaf(qs, c.w, sTu);
                sTuv = fmaf(qt, c.w, sTuv);
            }
            #pragma unroll
            for (int o = 16; o; o >>= 1) {
                sT   += __shfl_xor_sync(0xffffffffu, sT,   o);
                sTu  += __shfl_xor_sync(0xffffffffu, sTu,  o);
                sTv  += __shfl_xor_sync(0xffffffffu, sTv,  o);
                sTuv += __shfl_xor_sync(0xffffffffu, sTuv, o);
            }
            if (lane == 0) {
                float T   = sT   * inv_v;
                float Tu  = sTu  * inv_v;
                float Tv  = sTv  * inv_v;
                float Tuv = sTuv * inv_v;
                #pragma unroll
                for (int p2 = 0; p2 < NPH; p2++) {
                    float4 ab = sint4[p2];
                    float tp = fex2(fmaf(u, ab.x, ab.y));
                    T  += tp;
                    Tu = fmaf(ab.z, tp, Tu);
                }
                float invT = frcp(T);
                float hu = Tu * invT;
                float hv = Tv * invT;
                float4 o;
                // fold the exact quadratics into value + derivatives
                o.x = flg2(T) + k_u * u * u + k_v * v * v;
                o.y = hu * IE + 2.0f * k_u * u;
                o.z = hv * IE + 2.0f * k_v * v;
                o.w = (Tuv * invT - hu * hv) * IE;
                g_table[node] = o;
            }
        }
    }

    // ---- pre-barrier: ALL phase-2 prep (pm, cells, Hermite bases) ----
    float pmv[2];
    int   baseA[2];
    float AuB[2][4], AvB[2][4];
    #pragma unroll
    for (int i = 0; i < 2; i++) {
        float u = (i == 0) ? u2.x : u2.y;
        float v = (i == 0) ? v2.x : v2.y;
        pmv[i] = 2.0f * flg2(v);                // quadratics folded into table

        float su = u * (float)NUI;
        int iu = (int)su; iu = min(max(iu, 0), NUI - 1);
        float s = su - (float)iu;
        float sv = (v - V0C) * ((float)NVI / 0.3f);
        int iv = (int)sv; iv = min(max(iv, 0), NVI - 1);
        float t = sv - (float)iv;
        baseA[i] = iu * NVN + iv;

        float ss = s * s, s3 = ss * s;
        AuB[i][0] = 2.0f * s3 - 3.0f * ss + 1.0f;
        AuB[i][1] = (s3 - 2.0f * ss + s) * HUC;
        AuB[i][2] = 3.0f * ss - 2.0f * s3;
        AuB[i][3] = (s3 - ss) * HUC;
        float tt = t * t, t3 = tt * t;
        AvB[i][0] = 2.0f * t3 - 3.0f * tt + 1.0f;
        AvB[i][1] = (t3 - 2.0f * tt + t) * HVC;
        AvB[i][2] = 3.0f * tt - 2.0f * t3;
        AvB[i][3] = (t3 - tt) * HVC;
    }

    // ---- device-wide barrier (304 co-resident blocks) ----
    if (tid == 0) {
        __threadfence();
        atomicAdd(&g_sync, 1u);
        while (ld_acq(&g_sync) < NBLK) __nanosleep(64);
    }
    __syncthreads();

    // ---- phase 2: only table reads + dot products remain ----
    float acc = 0.0f;
    if (havept) {
        #pragma unroll
        for (int i = 0; i < 2; i++) {
            const float4* tb = g_table + baseA[i];
            float4 c00 = __ldg(tb);
            float4 c01 = __ldg(tb + 1);
            float4 c10 = __ldg(tb + NVN);
            float4 c11 = __ldg(tb + NVN + 1);

            float Av0 = AvB[i][0], Av1 = AvB[i][1];
            float Av2 = AvB[i][2], Av3 = AvB[i][3];
            float P0 = Av0*c00.x + Av1*c00.z + Av2*c01.x + Av3*c01.z;
            float P1 = Av0*c00.y + Av1*c00.w + Av2*c01.y + Av3*c01.w;
            float P2 = Av0*c10.x + Av1*c10.z + Av2*c11.x + Av3*c11.z;
            float P3 = Av0*c10.y + Av1*c10.w + Av2*c11.y + Av3*c11.w;
            float f  = AuB[i][0]*P0 + AuB[i][1]*P1
                     + AuB[i][2]*P2 + AuB[i][3]*P3;

            acc += pmv[i] + f;
        }
    }

    // ---- block reduction, then one float atomic per block ----
    #pragma unroll
    for (int o = 16; o > 0; o >>= 1) acc += __shfl_down_sync(0xffffffffu, acc, o);
    if (lane == 0) sRed[wid] = acc;
    __syncthreads();
    if (tid == 0) {
        float bs = 0.0f;
        #pragma unroll
        for (int w = 0; w < TPB / 32; w++) bs += sRed[w];
        atomicAdd(&g_accum, bs);
        __threadfence();
        unsigned int ticket = atomicAdd(&g_count, 1u);
        s_last = (ticket == NBLK - 1);
    }
    __syncthreads();

    if (s_last && tid == 0) {
        float a;
        asm volatile("ld.global.acquire.gpu.f32 %0, [%1];"
                     : "=f"(a) : "l"(&g_accum));
        out[0] = -a * (LN2 / (float)MDATA);
        g_accum = 0.0f;   // reset for next graph replay
        g_sync  = 0;
        g_count = 0;
    }
}

extern "C" void kernel_launch(void* const* d_in, const int* in_sizes, int n_in,
                              void* d_out, int out_size) {
    (void)in_sizes; (void)n_in; (void)out_size;
    bimm_fused_kernel<<<NBLK, TPB>>>(
        (const float*)d_in[0], (const float*)d_in[1], (const float*)d_in[2],
        (const float*)d_in[3], (const float*)d_in[4], (const float*)d_in[5],
        (const float*)d_in[6], (const float*)d_in[7], (const float*)d_in[8],
        (float*)d_out);
}